// round 3
// baseline (speedup 1.0000x reference)
#include <cuda_runtime.h>

#define N_NODES 8192
#define F_DIM   256
#define E_EDGES 262144
#define ADJ_ROW_WORDS (N_NODES / 32)              // 256
#define ADJ_WORDS     (N_NODES * ADJ_ROW_WORDS)   // 2,097,152 words = 8MB
#define NTILES 64                                 // 8192 / 128
#define NPAIRS (NTILES * (NTILES + 1) / 2)        // 2080

// ---------------- scratch (device globals; no allocation allowed) ----------
__device__ int      g_is32;                       // 1 if integer inputs are int32
__device__ int      g_ei[2 * E_EDGES];            // normalized edge index (int32)
__device__ float    g_mean[F_DIM];
__device__ float    g_w[N_NODES];
__device__ float    g_cov[F_DIM * F_DIM];
__device__ float    g_cor[F_DIM * F_DIM];
__device__ float    g_z2[N_NODES * F_DIM];        // 8 MB
__device__ float    g_nrm[N_NODES];
__device__ unsigned g_adj[ADJ_WORDS];             // 8 MB bitmask
__device__ float    g_scores[N_NODES];
__device__ float    g_deg[N_NODES];
__device__ double   g_penalty;

// ---------------- dtype detection ------------------------------------------
__global__ void detect_kernel(const void* __restrict__ ei_raw) {
    const long long* p = (const long long*)ei_raw;
    int bad = 0;
    for (int k = 0; k < 128; k++) {
        long long v = p[k];
        if (v < 0 || v >= N_NODES) bad = 1;
    }
    g_is32 = bad;
}

// ---------------- normalize edges to int32 ---------------------------------
__global__ void convert_kernel(const void* __restrict__ ei_raw) {
    int idx = blockIdx.x * blockDim.x + threadIdx.x;
    if (idx >= 2 * E_EDGES) return;
    int v;
    if (g_is32) v = ((const int*)ei_raw)[idx];
    else        v = (int)((const long long*)ei_raw)[idx];
    v = min(max(v, 0), N_NODES - 1);
    g_ei[idx] = v;
}

// ---------------- zero scratch ---------------------------------------------
__global__ void zero_kernel() {
    int i = blockIdx.x * blockDim.x + threadIdx.x;
    int stride = gridDim.x * blockDim.x;
    for (int idx = i; idx < ADJ_WORDS; idx += stride) g_adj[idx] = 0u;
    for (int idx = i; idx < F_DIM * F_DIM; idx += stride) g_cov[idx] = 0.f;
    if (i < F_DIM) g_mean[i] = 0.f;
    if (i < N_NODES) { g_scores[i] = 0.f; g_deg[i] = 0.f; }
    if (i == 0) g_penalty = 0.0;
}

// ---------------- column sums (-> mean) ------------------------------------
__global__ void mean_kernel(const float* __restrict__ z) {
    int f = threadIdx.x;                 // 256 threads = one per feature
    int r0 = blockIdx.x * 128;           // 64 blocks x 128 rows
    float acc = 0.f;
    for (int r = 0; r < 128; r++) acc += z[(r0 + r) * F_DIM + f];
    atomicAdd(&g_mean[f], acc);
}

// ---------------- scale mean, compute per-node weight w --------------------
__global__ void prep_kernel(const void* __restrict__ k2u_raw,
                            const void* __restrict__ u2k_raw) {
    int i = blockIdx.x * blockDim.x + threadIdx.x;
    if (i < F_DIM) g_mean[i] *= (1.f / (float)N_NODES);
    if (i < N_NODES) {
        float fa, fb;
        if (g_is32) {
            fa = (float)((const int*)k2u_raw)[i];
            fb = (float)((const int*)u2k_raw)[i];
        } else {
            fa = (float)((const long long*)k2u_raw)[i];
            fb = (float)((const long long*)u2k_raw)[i];
        }
        float a = powf(0.9f, fa);
        float b = powf(0.9f, fb);
        g_w[i] = a + 1.f - b;
    }
}

// ---------------- cov = zm^T zm  (F x F, K = N, split-K=4) -----------------
__global__ void cov_kernel(const float* __restrict__ z) {
    __shared__ float A[32][33];
    __shared__ float B[32][33];
    __shared__ float ma[32], mb[32];
    int a0 = blockIdx.y * 32, b0 = blockIdx.x * 32;
    int t = threadIdx.x;
    if (t < 32) ma[t] = g_mean[a0 + t];
    else if (t < 64) mb[t - 32] = g_mean[b0 + t - 32];
    __syncthreads();

    float acc00 = 0.f, acc01 = 0.f, acc10 = 0.f, acc11 = 0.f;
    int r0 = blockIdx.z * (N_NODES / 4);
    int tx = t & 15, ty = t >> 4;
    for (int rc = 0; rc < N_NODES / 4; rc += 32) {
#pragma unroll
        for (int q = 0; q < 4; q++) {
            int idx = t + q * 256;
            int rr = idx >> 5, cc = idx & 31;
            int gr = r0 + rc + rr;
            A[rr][cc] = z[gr * F_DIM + a0 + cc] - ma[cc];
            B[rr][cc] = z[gr * F_DIM + b0 + cc] - mb[cc];
        }
        __syncthreads();
#pragma unroll
        for (int kk = 0; kk < 32; kk++) {
            float av0 = A[kk][ty * 2], av1 = A[kk][ty * 2 + 1];
            float bv0 = B[kk][tx * 2], bv1 = B[kk][tx * 2 + 1];
            acc00 += av0 * bv0; acc01 += av0 * bv1;
            acc10 += av1 * bv0; acc11 += av1 * bv1;
        }
        __syncthreads();
    }
    atomicAdd(&g_cov[(a0 + ty * 2 + 0) * F_DIM + b0 + tx * 2 + 0], acc00);
    atomicAdd(&g_cov[(a0 + ty * 2 + 0) * F_DIM + b0 + tx * 2 + 1], acc01);
    atomicAdd(&g_cov[(a0 + ty * 2 + 1) * F_DIM + b0 + tx * 2 + 0], acc10);
    atomicAdd(&g_cov[(a0 + ty * 2 + 1) * F_DIM + b0 + tx * 2 + 1], acc11);
}

// ---------------- correlation matrix ---------------------------------------
__global__ void cor_kernel() {
    int a = blockIdx.x, b = threadIdx.x;
    float denom = sqrtf(g_cov[a * F_DIM + a]) * sqrtf(g_cov[b * F_DIM + b]);
    float v = g_cov[a * F_DIM + b] / denom;
    if (isnan(v)) v = 0.f;
    v = fminf(1.f, fmaxf(-1.f, v));
    if (a == b) v = 0.f;
    g_cor[a * F_DIM + b] = v;
}

// ---------------- z2 = z + EPS * (w .* zm) @ cor ---------------------------
__global__ void z2_kernel(const float* __restrict__ z) {
    __shared__ float Ws[16][68];
    __shared__ float Cs[16][68];
    int r0 = blockIdx.y * 64, c0 = blockIdx.x * 64;
    int t = threadIdx.x;
    int tx = t & 15, ty = t >> 4;
    float acc[4][4] = {};
    for (int k0 = 0; k0 < F_DIM; k0 += 16) {
#pragma unroll
        for (int q = 0; q < 4; q++) {
            int idx = t + q * 256;                 // 0..1023
            int row = idx >> 4, kk = idx & 15;
            Ws[kk][row] = g_w[r0 + row] *
                (z[(r0 + row) * F_DIM + k0 + kk] - g_mean[k0 + kk]);
            int kk2 = idx >> 6, cc = idx & 63;
            Cs[kk2][cc] = g_cor[(k0 + kk2) * F_DIM + c0 + cc];
        }
        __syncthreads();
#pragma unroll
        for (int kk = 0; kk < 16; kk++) {
            float4 av = *(const float4*)&Ws[kk][ty * 4];
            float4 bv = *(const float4*)&Cs[kk][tx * 4];
            float a4[4] = {av.x, av.y, av.z, av.w};
            float b4[4] = {bv.x, bv.y, bv.z, bv.w};
#pragma unroll
            for (int i = 0; i < 4; i++)
#pragma unroll
                for (int j = 0; j < 4; j++)
                    acc[i][j] += a4[i] * b4[j];
        }
        __syncthreads();
    }
#pragma unroll
    for (int i = 0; i < 4; i++)
#pragma unroll
        for (int j = 0; j < 4; j++) {
            int r = r0 + ty * 4 + i, c = c0 + tx * 4 + j;
            g_z2[r * F_DIM + c] = z[r * F_DIM + c] + 0.01f * acc[i][j];
        }
}

// ---------------- per-node L2 norm of z2 -----------------------------------
__global__ void norm_kernel() {
    int n = blockIdx.x;
    int t = threadIdx.x;                      // 64 threads
    float4 v = *(const float4*)&g_z2[n * F_DIM + t * 4];
    float s = v.x * v.x + v.y * v.y + v.z * v.z + v.w * v.w;
#pragma unroll
    for (int o = 16; o; o >>= 1) s += __shfl_down_sync(0xffffffffu, s, o);
    __shared__ float sw[2];
    if ((t & 31) == 0) sw[t >> 5] = s;
    __syncthreads();
    if (t == 0) g_nrm[n] = fmaxf(sqrtf(sw[0] + sw[1]), 1e-8f);
}

// ---------------- adjacency bitmask from edges -----------------------------
__global__ void adj_kernel() {
    int e = blockIdx.x * blockDim.x + threadIdx.x;
    if (e >= E_EDGES) return;
    int i = g_ei[e];
    int j = g_ei[E_EDGES + e];
    atomicOr(&g_adj[i * ADJ_ROW_WORDS + (j >> 5)], 1u << (j & 31));
    atomicOr(&g_adj[j * ADJ_ROW_WORDS + (i >> 5)], 1u << (i & 31));
}

// ---------------- per-edge cosine, scatter by source -----------------------
__global__ void edge_kernel() {
    int warp = (blockIdx.x * blockDim.x + threadIdx.x) >> 5;
    int lane = threadIdx.x & 31;
    if (warp >= E_EDGES) return;
    int i = g_ei[warp];
    int j = g_ei[E_EDGES + warp];
    const float4* zi = (const float4*)(g_z2 + i * F_DIM);
    const float4* zj = (const float4*)(g_z2 + j * F_DIM);
    float acc = 0.f;
#pragma unroll
    for (int q = 0; q < 2; q++) {
        float4 a = zi[lane * 2 + q];
        float4 b = zj[lane * 2 + q];
        acc += a.x * b.x + a.y * b.y + a.z * b.z + a.w * b.w;
    }
#pragma unroll
    for (int o = 16; o; o >>= 1) acc += __shfl_down_sync(0xffffffffu, acc, o);
    if (lane == 0) {
        float sim = acc / (g_nrm[i] * g_nrm[j]);
        atomicAdd(&g_scores[i], sim);
        atomicAdd(&g_deg[i], 1.0f);
    }
}

// ---------------- big GEMM z2 @ z2^T with fused masked-threshold sum -------
// Packed f32x2 FFMA2 path. Symmetric: linear grid over upper-tri tiles only.
__global__ void __launch_bounds__(256, 2) penalty_kernel() {
    // decode linear tile index -> (rb, cb), rb <= cb
    int rb = 0, cb;
    {
        int rem = blockIdx.x;
        int width = NTILES;
        while (rem >= width) { rem -= width; width--; rb++; }
        cb = rb + rem;
    }

    __shared__ float As[2][8][264];     // A values DUPLICATED: {a,a} pairs
    __shared__ float Bs[2][8][132];
    __shared__ unsigned adjS[128][4];
    __shared__ float red[8];

    int t = threadIdx.x;
    int tx = t & 15, ty = t >> 4;
    int r0 = rb * 128, c0 = cb * 128;
    int lr = t >> 1;                   // row within tile 0..127
    int lh = (t & 1) * 4;              // 4-float half of the 8-wide k-chunk

    unsigned long long acc[8][4] = {}; // packed {lo,hi} fp32 pairs, all zeros

    // chunk 0
    {
        float4 a = *(const float4*)&g_z2[(r0 + lr) * F_DIM + lh];
        float4 b = *(const float4*)&g_z2[(c0 + lr) * F_DIM + lh];
        *(float2*)&As[0][lh + 0][2 * lr] = make_float2(a.x, a.x);
        *(float2*)&As[0][lh + 1][2 * lr] = make_float2(a.y, a.y);
        *(float2*)&As[0][lh + 2][2 * lr] = make_float2(a.z, a.z);
        *(float2*)&As[0][lh + 3][2 * lr] = make_float2(a.w, a.w);
        Bs[0][lh + 0][lr] = b.x; Bs[0][lh + 1][lr] = b.y;
        Bs[0][lh + 2][lr] = b.z; Bs[0][lh + 3][lr] = b.w;
    }
    __syncthreads();

    for (int ch = 0; ch < 32; ch++) {
        int cur = ch & 1;
        float4 na, nb;
        if (ch < 31) {
            int k0 = (ch + 1) * 8;
            na = *(const float4*)&g_z2[(r0 + lr) * F_DIM + k0 + lh];
            nb = *(const float4*)&g_z2[(c0 + lr) * F_DIM + k0 + lh];
        }
#pragma unroll
        for (int kk = 0; kk < 8; kk++) {
            // A: 8 duplicated pairs (broadcast within half-warp)
            const unsigned long long* Ap =
                (const unsigned long long*)&As[cur][kk][ty * 16];
            // B: 4 packed pairs = 8 floats
            const unsigned long long* Bp =
                (const unsigned long long*)&Bs[cur][kk][tx * 8];
            unsigned long long a2[8], b2[4];
#pragma unroll
            for (int i = 0; i < 8; i++) a2[i] = Ap[i];
#pragma unroll
            for (int j = 0; j < 4; j++) b2[j] = Bp[j];
#pragma unroll
            for (int i = 0; i < 8; i++)
#pragma unroll
                for (int j = 0; j < 4; j++)
                    asm("fma.rn.f32x2 %0, %1, %2, %0;"
                        : "+l"(acc[i][j]) : "l"(a2[i]), "l"(b2[j]));
        }
        if (ch < 31) {
            int nxt = cur ^ 1;
            *(float2*)&As[nxt][lh + 0][2 * lr] = make_float2(na.x, na.x);
            *(float2*)&As[nxt][lh + 1][2 * lr] = make_float2(na.y, na.y);
            *(float2*)&As[nxt][lh + 2][2 * lr] = make_float2(na.z, na.z);
            *(float2*)&As[nxt][lh + 3][2 * lr] = make_float2(na.w, na.w);
            Bs[nxt][lh + 0][lr] = nb.x; Bs[nxt][lh + 1][lr] = nb.y;
            Bs[nxt][lh + 2][lr] = nb.z; Bs[nxt][lh + 3][lr] = nb.w;
            __syncthreads();
        }
    }

    // adjacency words for this tile
#pragma unroll
    for (int q = 0; q < 2; q++) {
        int idx = t + q * 256;
        int row = idx >> 2, w = idx & 3;
        adjS[row][w] = g_adj[(r0 + row) * ADJ_ROW_WORDS + cb * 4 + w];
    }
    __syncthreads();

    float psum = 0.f;
#pragma unroll
    for (int i = 0; i < 8; i++) {
        int mi = ty * 8 + i;
        unsigned w0 = adjS[mi][(tx * 8) >> 5];   // all 8 j's share one word range?
#pragma unroll
        for (int j = 0; j < 4; j++) {
            int nj = tx * 8 + 2 * j;
            unsigned wbits = adjS[mi][nj >> 5];
            float lo = __uint_as_float((unsigned)(acc[i][j] & 0xffffffffull));
            float hi = __uint_as_float((unsigned)(acc[i][j] >> 32));
            bool adj0 = (wbits >> (nj & 31)) & 1u;
            bool adj1 = (wbits >> ((nj + 1) & 31)) & 1u;
            if (!adj0 && lo > 0.8f) psum += lo;
            if (!adj1 && hi > 0.8f) psum += hi;
        }
        (void)w0;
    }
#pragma unroll
    for (int o = 16; o; o >>= 1) psum += __shfl_down_sync(0xffffffffu, psum, o);
    if ((t & 31) == 0) red[t >> 5] = psum;
    __syncthreads();
    if (t == 0) {
        float s = 0.f;
#pragma unroll
        for (int q = 0; q < 8; q++) s += red[q];
        double wgt = (rb == cb) ? 1.0 : 2.0;
        atomicAdd(&g_penalty, (double)s * wgt);
    }
}

// ---------------- finalize --------------------------------------------------
__global__ void final_kernel(float* __restrict__ out) {
    int t = threadIdx.x;
    float acc = 0.f;
    for (int n = t; n < N_NODES; n += 256) {
        float d = g_deg[n];
        if (d == 0.f) d = 1.f;
        acc += g_scores[n] / d;
    }
#pragma unroll
    for (int o = 16; o; o >>= 1) acc += __shfl_down_sync(0xffffffffu, acc, o);
    __shared__ float red[8];
    if ((t & 31) == 0) red[t >> 5] = acc;
    __syncthreads();
    if (t == 0) {
        float tot = 0.f;
        for (int q = 0; q < 8; q++) tot += red[q];
        double hom = -(double)tot / (double)N_NODES;
        double pen = g_penalty / ((double)N_NODES * (double)N_NODES);
        out[0] = (float)(hom + pen);
    }
}

// ---------------- launch ----------------------------------------------------
extern "C" void kernel_launch(void* const* d_in, const int* in_sizes, int n_in,
                              void* d_out, int out_size) {
    const float* z       = (const float*)d_in[0];
    // d_in[1] = x_hat (unused by reference)
    const void*  ei_raw  = d_in[2];
    const void*  k2u_raw = d_in[3];
    const void*  u2k_raw = d_in[4];
    float* out = (float*)d_out;

    detect_kernel<<<1, 1>>>(ei_raw);
    convert_kernel<<<(2 * E_EDGES + 255) / 256, 256>>>(ei_raw);
    zero_kernel<<<4096, 256>>>();
    mean_kernel<<<64, 256>>>(z);
    prep_kernel<<<32, 256>>>(k2u_raw, u2k_raw);
    cov_kernel<<<dim3(8, 8, 4), 256>>>(z);
    cor_kernel<<<256, 256>>>();
    z2_kernel<<<dim3(4, 128), 256>>>(z);
    norm_kernel<<<N_NODES, 64>>>();
    adj_kernel<<<E_EDGES / 256, 256>>>();
    edge_kernel<<<E_EDGES * 32 / 256, 256>>>();
    penalty_kernel<<<NPAIRS, 256>>>();
    final_kernel<<<1, 256>>>(out);
}

// round 7
// speedup vs baseline: 2.1671x; 2.1671x over previous
#include <cuda_runtime.h>
#include <cuda_bf16.h>
#include <cstdint>

#define N_NODES 8192
#define F_DIM   256
#define E_EDGES 262144
#define ADJ_ROW_WORDS (N_NODES / 32)              // 256
#define ADJ_WORDS     (N_NODES * ADJ_ROW_WORDS)   // 2,097,152 words = 8MB
#define NTILES 64                                 // 8192 / 128
#define NPAIRS (NTILES * (NTILES + 1) / 2)        // 2080

// ---------------- scratch (device globals; no allocation allowed) ----------
__device__ int           g_is32;
__device__ int           g_ei[2 * E_EDGES];
__device__ float         g_mean[F_DIM];
__device__ float         g_w[N_NODES];
__device__ float         g_cov[F_DIM * F_DIM];
__device__ float         g_cor[F_DIM * F_DIM];
__device__ float         g_z2[N_NODES * F_DIM];       // 8 MB fp32
__device__ __nv_bfloat16 g_zb[N_NODES * F_DIM];       // 4 MB bf16 copy
__device__ float         g_nrm[N_NODES];
__device__ unsigned      g_adj[ADJ_WORDS];            // 8 MB bitmask
__device__ float         g_scores[N_NODES];
__device__ float         g_deg[N_NODES];
__device__ double        g_penalty;

__device__ __forceinline__ uint32_t smem_u32(const void* p) {
    uint32_t a;
    asm("{ .reg .u64 t; cvta.to.shared.u64 t, %1; cvt.u32.u64 %0, t; }"
        : "=r"(a) : "l"(p));
    return a;
}

// ---------------- dtype detection ------------------------------------------
__global__ void detect_kernel(const void* __restrict__ ei_raw) {
    const long long* p = (const long long*)ei_raw;
    int bad = 0;
    for (int k = 0; k < 128; k++) {
        long long v = p[k];
        if (v < 0 || v >= N_NODES) bad = 1;
    }
    g_is32 = bad;
}

// ---------------- normalize edges to int32 ---------------------------------
__global__ void convert_kernel(const void* __restrict__ ei_raw) {
    int idx = blockIdx.x * blockDim.x + threadIdx.x;
    if (idx >= 2 * E_EDGES) return;
    int v;
    if (g_is32) v = ((const int*)ei_raw)[idx];
    else        v = (int)((const long long*)ei_raw)[idx];
    v = min(max(v, 0), N_NODES - 1);
    g_ei[idx] = v;
}

// ---------------- zero scratch ---------------------------------------------
__global__ void zero_kernel() {
    int i = blockIdx.x * blockDim.x + threadIdx.x;
    int stride = gridDim.x * blockDim.x;
    for (int idx = i; idx < ADJ_WORDS; idx += stride) g_adj[idx] = 0u;
    for (int idx = i; idx < F_DIM * F_DIM; idx += stride) g_cov[idx] = 0.f;
    if (i < F_DIM) g_mean[i] = 0.f;
    if (i < N_NODES) { g_scores[i] = 0.f; g_deg[i] = 0.f; }
    if (i == 0) g_penalty = 0.0;
}

// ---------------- column sums (-> mean) ------------------------------------
__global__ void mean_kernel(const float* __restrict__ z) {
    int f = threadIdx.x;
    int r0 = blockIdx.x * 128;
    float acc = 0.f;
    for (int r = 0; r < 128; r++) acc += z[(r0 + r) * F_DIM + f];
    atomicAdd(&g_mean[f], acc);
}

// ---------------- scale mean, compute per-node weight w --------------------
__global__ void prep_kernel(const void* __restrict__ k2u_raw,
                            const void* __restrict__ u2k_raw) {
    int i = blockIdx.x * blockDim.x + threadIdx.x;
    if (i < F_DIM) g_mean[i] *= (1.f / (float)N_NODES);
    if (i < N_NODES) {
        float fa, fb;
        if (g_is32) {
            fa = (float)((const int*)k2u_raw)[i];
            fb = (float)((const int*)u2k_raw)[i];
        } else {
            fa = (float)((const long long*)k2u_raw)[i];
            fb = (float)((const long long*)u2k_raw)[i];
        }
        float a = powf(0.9f, fa);
        float b = powf(0.9f, fb);
        g_w[i] = a + 1.f - b;
    }
}

// ---------------- cov = zm^T zm  (F x F, K = N, split-K=4) -----------------
__global__ void cov_kernel(const float* __restrict__ z) {
    __shared__ float A[32][33];
    __shared__ float B[32][33];
    __shared__ float ma[32], mb[32];
    int a0 = blockIdx.y * 32, b0 = blockIdx.x * 32;
    int t = threadIdx.x;
    if (t < 32) ma[t] = g_mean[a0 + t];
    else if (t < 64) mb[t - 32] = g_mean[b0 + t - 32];
    __syncthreads();

    float acc00 = 0.f, acc01 = 0.f, acc10 = 0.f, acc11 = 0.f;
    int r0 = blockIdx.z * (N_NODES / 4);
    int tx = t & 15, ty = t >> 4;
    for (int rc = 0; rc < N_NODES / 4; rc += 32) {
#pragma unroll
        for (int q = 0; q < 4; q++) {
            int idx = t + q * 256;
            int rr = idx >> 5, cc = idx & 31;
            int gr = r0 + rc + rr;
            A[rr][cc] = z[gr * F_DIM + a0 + cc] - ma[cc];
            B[rr][cc] = z[gr * F_DIM + b0 + cc] - mb[cc];
        }
        __syncthreads();
#pragma unroll
        for (int kk = 0; kk < 32; kk++) {
            float av0 = A[kk][ty * 2], av1 = A[kk][ty * 2 + 1];
            float bv0 = B[kk][tx * 2], bv1 = B[kk][tx * 2 + 1];
            acc00 += av0 * bv0; acc01 += av0 * bv1;
            acc10 += av1 * bv0; acc11 += av1 * bv1;
        }
        __syncthreads();
    }
    atomicAdd(&g_cov[(a0 + ty * 2 + 0) * F_DIM + b0 + tx * 2 + 0], acc00);
    atomicAdd(&g_cov[(a0 + ty * 2 + 0) * F_DIM + b0 + tx * 2 + 1], acc01);
    atomicAdd(&g_cov[(a0 + ty * 2 + 1) * F_DIM + b0 + tx * 2 + 0], acc10);
    atomicAdd(&g_cov[(a0 + ty * 2 + 1) * F_DIM + b0 + tx * 2 + 1], acc11);
}

// ---------------- correlation matrix ---------------------------------------
__global__ void cor_kernel() {
    int a = blockIdx.x, b = threadIdx.x;
    float denom = sqrtf(g_cov[a * F_DIM + a]) * sqrtf(g_cov[b * F_DIM + b]);
    float v = g_cov[a * F_DIM + b] / denom;
    if (isnan(v)) v = 0.f;
    v = fminf(1.f, fmaxf(-1.f, v));
    if (a == b) v = 0.f;
    g_cor[a * F_DIM + b] = v;
}

// ---------------- z2 = z + EPS * (w .* zm) @ cor  (+ bf16 copy) ------------
__global__ void z2_kernel(const float* __restrict__ z) {
    __shared__ float Ws[16][68];
    __shared__ float Cs[16][68];
    int r0 = blockIdx.y * 64, c0 = blockIdx.x * 64;
    int t = threadIdx.x;
    int tx = t & 15, ty = t >> 4;
    float acc[4][4] = {};
    for (int k0 = 0; k0 < F_DIM; k0 += 16) {
#pragma unroll
        for (int q = 0; q < 4; q++) {
            int idx = t + q * 256;
            int row = idx >> 4, kk = idx & 15;
            Ws[kk][row] = g_w[r0 + row] *
                (z[(r0 + row) * F_DIM + k0 + kk] - g_mean[k0 + kk]);
            int kk2 = idx >> 6, cc = idx & 63;
            Cs[kk2][cc] = g_cor[(k0 + kk2) * F_DIM + c0 + cc];
        }
        __syncthreads();
#pragma unroll
        for (int kk = 0; kk < 16; kk++) {
            float4 av = *(const float4*)&Ws[kk][ty * 4];
            float4 bv = *(const float4*)&Cs[kk][tx * 4];
            float a4[4] = {av.x, av.y, av.z, av.w};
            float b4[4] = {bv.x, bv.y, bv.z, bv.w};
#pragma unroll
            for (int i = 0; i < 4; i++)
#pragma unroll
                for (int j = 0; j < 4; j++)
                    acc[i][j] += a4[i] * b4[j];
        }
        __syncthreads();
    }
#pragma unroll
    for (int i = 0; i < 4; i++)
#pragma unroll
        for (int j = 0; j < 4; j++) {
            int r = r0 + ty * 4 + i, c = c0 + tx * 4 + j;
            float v = z[r * F_DIM + c] + 0.01f * acc[i][j];
            g_z2[r * F_DIM + c] = v;
            g_zb[r * F_DIM + c] = __float2bfloat16(v);
        }
}

// ---------------- per-node L2 norm of z2 -----------------------------------
__global__ void norm_kernel() {
    int n = blockIdx.x;
    int t = threadIdx.x;                      // 64 threads
    float4 v = *(const float4*)&g_z2[n * F_DIM + t * 4];
    float s = v.x * v.x + v.y * v.y + v.z * v.z + v.w * v.w;
#pragma unroll
    for (int o = 16; o; o >>= 1) s += __shfl_down_sync(0xffffffffu, s, o);
    __shared__ float sw[2];
    if ((t & 31) == 0) sw[t >> 5] = s;
    __syncthreads();
    if (t == 0) g_nrm[n] = fmaxf(sqrtf(sw[0] + sw[1]), 1e-8f);
}

// ---------------- adjacency bitmask from edges -----------------------------
__global__ void adj_kernel() {
    int e = blockIdx.x * blockDim.x + threadIdx.x;
    if (e >= E_EDGES) return;
    int i = g_ei[e];
    int j = g_ei[E_EDGES + e];
    atomicOr(&g_adj[i * ADJ_ROW_WORDS + (j >> 5)], 1u << (j & 31));
    atomicOr(&g_adj[j * ADJ_ROW_WORDS + (i >> 5)], 1u << (i & 31));
}

// ---------------- per-edge cosine, scatter by source -----------------------
__global__ void edge_kernel() {
    int warp = (blockIdx.x * blockDim.x + threadIdx.x) >> 5;
    int lane = threadIdx.x & 31;
    if (warp >= E_EDGES) return;
    int i = g_ei[warp];
    int j = g_ei[E_EDGES + warp];
    const float4* zi = (const float4*)(g_z2 + i * F_DIM);
    const float4* zj = (const float4*)(g_z2 + j * F_DIM);
    float acc = 0.f;
#pragma unroll
    for (int q = 0; q < 2; q++) {
        float4 a = zi[lane * 2 + q];
        float4 b = zj[lane * 2 + q];
        acc += a.x * b.x + a.y * b.y + a.z * b.z + a.w * b.w;
    }
#pragma unroll
    for (int o = 16; o; o >>= 1) acc += __shfl_down_sync(0xffffffffu, acc, o);
    if (lane == 0) {
        float sim = acc / (g_nrm[i] * g_nrm[j]);
        atomicAdd(&g_scores[i], sim);
        atomicAdd(&g_deg[i], 1.0f);
    }
}

// ---------------- penalty GEMM: bf16 mma.sync (sm_80+ path) ----------------
// D(128x128) = A(128x256) @ B(128x256)^T, K processed in two 128-wide phases.
// SMEM: A tile [128][128] bf16 (32KB) + B tile (32KB), XOR-swizzled 16B units.
// 8 warps: 2 (m) x 4 (n), each computes 64x32 via m16n8k16 fragments.
#define PB_B_OFF 32768
#define PB_TOTAL 65536

__global__ void __launch_bounds__(256) penalty_mma_kernel() {
    extern __shared__ char smem[];
    uint32_t sb = smem_u32(smem);
    int t = threadIdx.x, wid = t >> 5, lane = t & 31;

    int rb = 0, cb;
    {
        int rem = blockIdx.x;
        int width = NTILES;
        while (rem >= width) { rem -= width; width--; rb++; }
        cb = rb + rem;
    }
    int r0 = rb * 128, c0 = cb * 128;

    int wm = (wid >> 2) * 64;          // warp m offset (0 or 64)
    int wn = (wid & 3) * 32;           // warp n offset (0,32,64,96)

    float acc[4][4][4];                // [m-tile][n-tile][c0..c3]
#pragma unroll
    for (int i = 0; i < 4; i++)
#pragma unroll
        for (int j = 0; j < 4; j++)
#pragma unroll
            for (int k = 0; k < 4; k++) acc[i][j][k] = 0.f;

    for (int ph = 0; ph < 2; ph++) {
        if (ph) __syncthreads();
        // load 128x128 bf16 A and B chunks, swizzled (unit ^= row&7)
        for (int q = t; q < 2048; q += 256) {
            int row = q >> 4, unit = q & 15;
            uint32_t off = (uint32_t)(row * 256 + ((unit ^ (row & 7)) << 4));
            *(uint4*)(smem + off) =
                *(const uint4*)(g_zb + (r0 + row) * F_DIM + ph * 128 + unit * 8);
            *(uint4*)(smem + PB_B_OFF + off) =
                *(const uint4*)(g_zb + (c0 + row) * F_DIM + ph * 128 + unit * 8);
        }
        __syncthreads();

#pragma unroll
        for (int ks = 0; ks < 128; ks += 16) {
            // A fragments: one ldmatrix.x4 per m-tile
            uint32_t a[4][4];
#pragma unroll
            for (int mt = 0; mt < 4; mt++) {
                int row = wm + mt * 16 + (lane & 15);
                int kc = ks + ((lane >> 4) << 3);
                uint32_t addr = sb + (uint32_t)(row * 256 +
                               ((((kc >> 3)) ^ (row & 7)) << 4));
                asm volatile(
                    "ldmatrix.sync.aligned.m8n8.x4.shared.b16 {%0,%1,%2,%3}, [%4];"
                    : "=r"(a[mt][0]), "=r"(a[mt][1]), "=r"(a[mt][2]), "=r"(a[mt][3])
                    : "r"(addr));
            }
            // B fragments: one ldmatrix.x4 covers two n-tiles
            uint32_t b[4][2];
#pragma unroll
            for (int pr = 0; pr < 2; pr++) {
                int row = wn + pr * 16 + ((lane >> 4) << 3) + (lane & 7);
                int kc = ks + (((lane >> 3) & 1) << 3);
                uint32_t addr = sb + PB_B_OFF + (uint32_t)(row * 256 +
                               ((((kc >> 3)) ^ (row & 7)) << 4));
                asm volatile(
                    "ldmatrix.sync.aligned.m8n8.x4.shared.b16 {%0,%1,%2,%3}, [%4];"
                    : "=r"(b[pr * 2][0]), "=r"(b[pr * 2][1]),
                      "=r"(b[pr * 2 + 1][0]), "=r"(b[pr * 2 + 1][1])
                    : "r"(addr));
            }
#pragma unroll
            for (int mt = 0; mt < 4; mt++)
#pragma unroll
                for (int nt = 0; nt < 4; nt++)
                    asm volatile(
                        "mma.sync.aligned.m16n8k16.row.col.f32.bf16.bf16.f32 "
                        "{%0,%1,%2,%3}, {%4,%5,%6,%7}, {%8,%9}, {%0,%1,%2,%3};"
                        : "+f"(acc[mt][nt][0]), "+f"(acc[mt][nt][1]),
                          "+f"(acc[mt][nt][2]), "+f"(acc[mt][nt][3])
                        : "r"(a[mt][0]), "r"(a[mt][1]), "r"(a[mt][2]), "r"(a[mt][3]),
                          "r"(b[nt][0]), "r"(b[nt][1]));
        }
    }

    // fused epilogue: adjacency mask + threshold + reduce
    // thread t covers rows (wm + mt*16 + lane/4) and +8; cols wn + nt*8 + 2*(lane%4)+h
    float psum = 0.f;
    int qr = lane >> 2, qc = (lane & 3) * 2;
    int wword = cb * 4 + (wid & 3);    // adjacency word index for this warp's 32 cols
#pragma unroll
    for (int mt = 0; mt < 4; mt++) {
        int lr0 = wm + mt * 16 + qr;
        unsigned w0 = g_adj[(r0 + lr0) * ADJ_ROW_WORDS + wword];
        unsigned w1 = g_adj[(r0 + lr0 + 8) * ADJ_ROW_WORDS + wword];
#pragma unroll
        for (int nt = 0; nt < 4; nt++) {
            int cbit = nt * 8 + qc;    // bit position within the 32-col word
            float v0 = acc[mt][nt][0], v1 = acc[mt][nt][1];
            float v2 = acc[mt][nt][2], v3 = acc[mt][nt][3];
            if (!((w0 >> cbit) & 1u) && v0 > 0.8f) psum += v0;
            if (!((w0 >> (cbit + 1)) & 1u) && v1 > 0.8f) psum += v1;
            if (!((w1 >> cbit) & 1u) && v2 > 0.8f) psum += v2;
            if (!((w1 >> (cbit + 1)) & 1u) && v3 > 0.8f) psum += v3;
        }
    }
#pragma unroll
    for (int o = 16; o; o >>= 1) psum += __shfl_down_sync(0xffffffffu, psum, o);
    __shared__ float red[8];
    if (lane == 0) red[wid] = psum;
    __syncthreads();
    if (t == 0) {
        float s = 0.f;
#pragma unroll
        for (int q = 0; q < 8; q++) s += red[q];
        double wgt = (rb == cb) ? 1.0 : 2.0;
        atomicAdd(&g_penalty, (double)s * wgt);
    }
}

// ---------------- finalize --------------------------------------------------
__global__ void final_kernel(float* __restrict__ out) {
    int t = threadIdx.x;
    float acc = 0.f;
    for (int n = t; n < N_NODES; n += 256) {
        float d = g_deg[n];
        if (d == 0.f) d = 1.f;
        acc += g_scores[n] / d;
    }
#pragma unroll
    for (int o = 16; o; o >>= 1) acc += __shfl_down_sync(0xffffffffu, acc, o);
    __shared__ float red[8];
    if ((t & 31) == 0) red[t >> 5] = acc;
    __syncthreads();
    if (t == 0) {
        float tot = 0.f;
        for (int q = 0; q < 8; q++) tot += red[q];
        double hom = -(double)tot / (double)N_NODES;
        double pen = g_penalty / ((double)N_NODES * (double)N_NODES);
        out[0] = (float)(hom + pen);
    }
}

// ---------------- launch ----------------------------------------------------
extern "C" void kernel_launch(void* const* d_in, const int* in_sizes, int n_in,
                              void* d_out, int out_size) {
    const float* z       = (const float*)d_in[0];
    const void*  ei_raw  = d_in[2];
    const void*  k2u_raw = d_in[3];
    const void*  u2k_raw = d_in[4];
    float* out = (float*)d_out;

    static int smem_set = 0;
    if (!smem_set) {
        cudaFuncSetAttribute(penalty_mma_kernel,
                             cudaFuncAttributeMaxDynamicSharedMemorySize,
                             PB_TOTAL);
        smem_set = 1;
    }

    detect_kernel<<<1, 1>>>(ei_raw);
    convert_kernel<<<(2 * E_EDGES + 255) / 256, 256>>>(ei_raw);
    zero_kernel<<<4096, 256>>>();
    mean_kernel<<<64, 256>>>(z);
    prep_kernel<<<32, 256>>>(k2u_raw, u2k_raw);
    cov_kernel<<<dim3(8, 8, 4), 256>>>(z);
    cor_kernel<<<256, 256>>>();
    z2_kernel<<<dim3(4, 128), 256>>>(z);
    norm_kernel<<<N_NODES, 64>>>();
    adj_kernel<<<E_EDGES / 256, 256>>>();
    edge_kernel<<<E_EDGES * 32 / 256, 256>>>();
    penalty_mma_kernel<<<NPAIRS, 256, PB_TOTAL>>>();
    final_kernel<<<1, 256>>>(out);
}

// round 8
// speedup vs baseline: 3.2996x; 1.5226x over previous
#include <cuda_runtime.h>
#include <cuda_bf16.h>
#include <cstdint>

#define N_NODES 8192
#define F_DIM   256
#define E_EDGES 262144
#define ADJ_ROW_WORDS (N_NODES / 32)              // 256
#define ADJ_WORDS     (N_NODES * ADJ_ROW_WORDS)   // 8MB
#define NTILES 64
#define NPAIRS (NTILES * (NTILES + 1) / 2)        // 2080
#define PB_B_OFF 32768
#define PB_TOTAL 65536

// ---------------- scratch ---------------------------------------------------
__device__ int           g_is32;
__device__ int           g_ei[2 * E_EDGES];
__device__ float         g_mean[F_DIM];
__device__ float         g_w[N_NODES];
__device__ float         g_cov[F_DIM * F_DIM];
__device__ __nv_bfloat16 g_corb[F_DIM * F_DIM];        // cor bf16
__device__ __nv_bfloat16 g_zmt[F_DIM * N_NODES];       // zm^T bf16 [256][8192]
__device__ __nv_bfloat16 g_wzmb[N_NODES * F_DIM];      // w*zm bf16 [8192][256]
__device__ __nv_bfloat16 g_zb[N_NODES * F_DIM];        // z2 bf16 [8192][256]
__device__ float         g_nrm[N_NODES];
__device__ unsigned      g_adj[ADJ_WORDS];
__device__ float         g_scores[N_NODES];
__device__ float         g_deg[N_NODES];
__device__ double        g_penalty;

__device__ __forceinline__ uint32_t smem_u32(const void* p) {
    uint32_t a;
    asm("{ .reg .u64 t; cvta.to.shared.u64 t, %1; cvt.u32.u64 %0, t; }"
        : "=r"(a) : "l"(p));
    return a;
}

// ---- shared HMMA inner loop: consumes current 128x128 A/B SMEM tiles -------
__device__ __forceinline__ void mma_tile_128(uint32_t sb, int wm, int wn,
                                             int lane, float acc[4][4][4]) {
#pragma unroll
    for (int ks = 0; ks < 128; ks += 16) {
        uint32_t a[4][4];
#pragma unroll
        for (int mt = 0; mt < 4; mt++) {
            int row = wm + mt * 16 + (lane & 15);
            int kc = ks + ((lane >> 4) << 3);
            uint32_t addr = sb + (uint32_t)(row * 256 +
                           ((((kc >> 3)) ^ (row & 7)) << 4));
            asm volatile(
                "ldmatrix.sync.aligned.m8n8.x4.shared.b16 {%0,%1,%2,%3}, [%4];"
                : "=r"(a[mt][0]), "=r"(a[mt][1]), "=r"(a[mt][2]), "=r"(a[mt][3])
                : "r"(addr));
        }
        uint32_t b[4][2];
#pragma unroll
        for (int pr = 0; pr < 2; pr++) {
            int row = wn + pr * 16 + ((lane >> 4) << 3) + (lane & 7);
            int kc = ks + (((lane >> 3) & 1) << 3);
            uint32_t addr = sb + PB_B_OFF + (uint32_t)(row * 256 +
                           ((((kc >> 3)) ^ (row & 7)) << 4));
            asm volatile(
                "ldmatrix.sync.aligned.m8n8.x4.shared.b16 {%0,%1,%2,%3}, [%4];"
                : "=r"(b[pr * 2][0]), "=r"(b[pr * 2][1]),
                  "=r"(b[pr * 2 + 1][0]), "=r"(b[pr * 2 + 1][1])
                : "r"(addr));
        }
#pragma unroll
        for (int mt = 0; mt < 4; mt++)
#pragma unroll
            for (int nt = 0; nt < 4; nt++)
                asm volatile(
                    "mma.sync.aligned.m16n8k16.row.col.f32.bf16.bf16.f32 "
                    "{%0,%1,%2,%3}, {%4,%5,%6,%7}, {%8,%9}, {%0,%1,%2,%3};"
                    : "+f"(acc[mt][nt][0]), "+f"(acc[mt][nt][1]),
                      "+f"(acc[mt][nt][2]), "+f"(acc[mt][nt][3])
                    : "r"(a[mt][0]), "r"(a[mt][1]), "r"(a[mt][2]), "r"(a[mt][3]),
                      "r"(b[nt][0]), "r"(b[nt][1]));
    }
}

// ---------------- dtype detection ------------------------------------------
__global__ void detect_kernel(const void* __restrict__ ei_raw) {
    const long long* p = (const long long*)ei_raw;
    long long v = p[threadIdx.x];
    int bad = (v < 0 || v >= N_NODES) ? 1 : 0;
    bad = __syncthreads_or(bad);
    if (threadIdx.x == 0) g_is32 = bad;
}

__global__ void convert_kernel(const void* __restrict__ ei_raw) {
    int idx = blockIdx.x * blockDim.x + threadIdx.x;
    if (idx >= 2 * E_EDGES) return;
    int v;
    if (g_is32) v = ((const int*)ei_raw)[idx];
    else        v = (int)((const long long*)ei_raw)[idx];
    v = min(max(v, 0), N_NODES - 1);
    g_ei[idx] = v;
}

__global__ void zero_kernel() {
    int i = blockIdx.x * blockDim.x + threadIdx.x;
    int stride = gridDim.x * blockDim.x;
    for (int idx = i; idx < ADJ_WORDS; idx += stride) g_adj[idx] = 0u;
    for (int idx = i; idx < F_DIM * F_DIM; idx += stride) g_cov[idx] = 0.f;
    if (i < F_DIM) g_mean[i] = 0.f;
    if (i < N_NODES) { g_scores[i] = 0.f; g_deg[i] = 0.f; }
    if (i == 0) g_penalty = 0.0;
}

__global__ void mean_kernel(const float* __restrict__ z) {
    int f = threadIdx.x;
    int r0 = blockIdx.x * 32;              // 256 blocks
    float acc = 0.f;
    for (int r = 0; r < 32; r++) acc += z[(r0 + r) * F_DIM + f];
    atomicAdd(&g_mean[f], acc);
}

__global__ void prep_kernel(const void* __restrict__ k2u_raw,
                            const void* __restrict__ u2k_raw) {
    int i = blockIdx.x * blockDim.x + threadIdx.x;
    if (i < F_DIM) g_mean[i] *= (1.f / (float)N_NODES);
    if (i < N_NODES) {
        float fa, fb;
        if (g_is32) {
            fa = (float)((const int*)k2u_raw)[i];
            fb = (float)((const int*)u2k_raw)[i];
        } else {
            fa = (float)((const long long*)k2u_raw)[i];
            fb = (float)((const long long*)u2k_raw)[i];
        }
        g_w[i] = powf(0.9f, fa) + 1.f - powf(0.9f, fb);
    }
}

// ---- build zm^T bf16 (for cov) and w*zm bf16 (for z2 GEMM) ----------------
__global__ void prep2_kernel(const float* __restrict__ z) {
    __shared__ __nv_bfloat16 S[64][258];
    int n0 = blockIdx.x * 64;
    int t = threadIdx.x;
    for (int idx = t; idx < 64 * 256; idx += 256) {
        int nl = idx >> 8, f = idx & 255;
        float zm = z[(n0 + nl) * F_DIM + f] - g_mean[f];
        S[nl][f] = __float2bfloat16(zm);
        g_wzmb[(n0 + nl) * F_DIM + f] = __float2bfloat16(g_w[n0 + nl] * zm);
    }
    __syncthreads();
    for (int idx = t; idx < 256 * 64; idx += 256) {
        int f = idx >> 6, nl = idx & 63;
        g_zmt[f * N_NODES + n0 + nl] = S[nl][f];
    }
}

// ---- cov = zmT @ zmT^T via HMMA; 3 symmetric tiles x 16 K-splits ----------
__global__ void __launch_bounds__(256) cov_mma_kernel() {
    extern __shared__ char smem[];
    uint32_t sb = smem_u32(smem);
    int t = threadIdx.x, wid = t >> 5, lane = t & 31;
    int tid = blockIdx.x;                    // 0:(0,0) 1:(0,1) 2:(1,1)
    int fb1 = (tid == 2) ? 1 : 0;
    int fb2 = (tid == 0) ? 0 : 1;
    int r0 = fb1 * 128, c0 = fb2 * 128;
    int k0 = blockIdx.y * 512;

    int wm = (wid >> 2) * 64, wn = (wid & 3) * 32;
    float acc[4][4][4] = {};

    for (int ph = 0; ph < 4; ph++) {
        if (ph) __syncthreads();
        for (int q = t; q < 2048; q += 256) {
            int row = q >> 4, unit = q & 15;
            uint32_t off = (uint32_t)(row * 256 + ((unit ^ (row & 7)) << 4));
            *(uint4*)(smem + off) =
                *(const uint4*)(g_zmt + (r0 + row) * N_NODES + k0 + ph * 128 + unit * 8);
            *(uint4*)(smem + PB_B_OFF + off) =
                *(const uint4*)(g_zmt + (c0 + row) * N_NODES + k0 + ph * 128 + unit * 8);
        }
        __syncthreads();
        mma_tile_128(sb, wm, wn, lane, acc);
    }

    int qr = lane >> 2, qc = (lane & 3) * 2;
#pragma unroll
    for (int mt = 0; mt < 4; mt++) {
#pragma unroll
        for (int nt = 0; nt < 4; nt++) {
            int r = r0 + wm + mt * 16 + qr;
            int c = c0 + wn + nt * 8 + qc;
            float v0 = acc[mt][nt][0], v1 = acc[mt][nt][1];
            float v2 = acc[mt][nt][2], v3 = acc[mt][nt][3];
            atomicAdd(&g_cov[r * F_DIM + c], v0);
            atomicAdd(&g_cov[r * F_DIM + c + 1], v1);
            atomicAdd(&g_cov[(r + 8) * F_DIM + c], v2);
            atomicAdd(&g_cov[(r + 8) * F_DIM + c + 1], v3);
            if (tid == 1) {
                atomicAdd(&g_cov[c * F_DIM + r], v0);
                atomicAdd(&g_cov[(c + 1) * F_DIM + r], v1);
                atomicAdd(&g_cov[c * F_DIM + r + 8], v2);
                atomicAdd(&g_cov[(c + 1) * F_DIM + r + 8], v3);
            }
        }
    }
}

__global__ void cor_kernel() {
    int a = blockIdx.x, b = threadIdx.x;
    float denom = sqrtf(g_cov[a * F_DIM + a]) * sqrtf(g_cov[b * F_DIM + b]);
    float v = g_cov[a * F_DIM + b] / denom;
    if (isnan(v)) v = 0.f;
    v = fminf(1.f, fmaxf(-1.f, v));
    if (a == b) v = 0.f;
    g_corb[a * F_DIM + b] = __float2bfloat16(v);
}

// ---- z2 = z + EPS * (w*zm) @ cor via HMMA; writes z2 bf16 -----------------
__global__ void __launch_bounds__(256) z2_mma_kernel(const float* __restrict__ z) {
    extern __shared__ char smem[];
    uint32_t sb = smem_u32(smem);
    int t = threadIdx.x, wid = t >> 5, lane = t & 31;
    int r0 = blockIdx.x * 128, c0 = blockIdx.y * 128;
    int wm = (wid >> 2) * 64, wn = (wid & 3) * 32;
    float acc[4][4][4] = {};

    for (int ph = 0; ph < 2; ph++) {
        if (ph) __syncthreads();
        for (int q = t; q < 2048; q += 256) {
            int row = q >> 4, unit = q & 15;
            uint32_t off = (uint32_t)(row * 256 + ((unit ^ (row & 7)) << 4));
            *(uint4*)(smem + off) =
                *(const uint4*)(g_wzmb + (r0 + row) * F_DIM + ph * 128 + unit * 8);
            *(uint4*)(smem + PB_B_OFF + off) =
                *(const uint4*)(g_corb + (c0 + row) * F_DIM + ph * 128 + unit * 8);
        }
        __syncthreads();
        mma_tile_128(sb, wm, wn, lane, acc);
    }

    int qr = lane >> 2, qc = (lane & 3) * 2;
#pragma unroll
    for (int mt = 0; mt < 4; mt++) {
#pragma unroll
        for (int nt = 0; nt < 4; nt++) {
            int r = r0 + wm + mt * 16 + qr;
            int c = c0 + wn + nt * 8 + qc;
            float v0 = z[r * F_DIM + c] + 0.01f * acc[mt][nt][0];
            float v1 = z[r * F_DIM + c + 1] + 0.01f * acc[mt][nt][1];
            float v2 = z[(r + 8) * F_DIM + c] + 0.01f * acc[mt][nt][2];
            float v3 = z[(r + 8) * F_DIM + c + 1] + 0.01f * acc[mt][nt][3];
            *(__nv_bfloat162*)(g_zb + r * F_DIM + c) = __floats2bfloat162_rn(v0, v1);
            *(__nv_bfloat162*)(g_zb + (r + 8) * F_DIM + c) = __floats2bfloat162_rn(v2, v3);
        }
    }
}

// ---------------- per-node L2 norm of z2 (bf16) -----------------------------
__global__ void norm_kernel() {
    int n = blockIdx.x;
    int t = threadIdx.x;                       // 64 threads
    uint4 v = ((const uint4*)(g_zb + n * F_DIM))[t];
    float s = 0.f;
    {
        float2 f0 = __bfloat1622float2(*(__nv_bfloat162*)&v.x);
        float2 f1 = __bfloat1622float2(*(__nv_bfloat162*)&v.y);
        float2 f2 = __bfloat1622float2(*(__nv_bfloat162*)&v.z);
        float2 f3 = __bfloat1622float2(*(__nv_bfloat162*)&v.w);
        s = f0.x * f0.x + f0.y * f0.y + f1.x * f1.x + f1.y * f1.y
          + f2.x * f2.x + f2.y * f2.y + f3.x * f3.x + f3.y * f3.y;
    }
#pragma unroll
    for (int o = 16; o; o >>= 1) s += __shfl_down_sync(0xffffffffu, s, o);
    __shared__ float sw[2];
    if ((t & 31) == 0) sw[t >> 5] = s;
    __syncthreads();
    if (t == 0) g_nrm[n] = fmaxf(sqrtf(sw[0] + sw[1]), 1e-8f);
}

__global__ void adj_kernel() {
    int e = blockIdx.x * blockDim.x + threadIdx.x;
    if (e >= E_EDGES) return;
    int i = g_ei[e];
    int j = g_ei[E_EDGES + e];
    atomicOr(&g_adj[i * ADJ_ROW_WORDS + (j >> 5)], 1u << (j & 31));
    atomicOr(&g_adj[j * ADJ_ROW_WORDS + (i >> 5)], 1u << (i & 31));
}

// ---------------- per-edge cosine (bf16 gathers) ----------------------------
__global__ void edge_kernel() {
    int warp = (blockIdx.x * blockDim.x + threadIdx.x) >> 5;
    int lane = threadIdx.x & 31;
    if (warp >= E_EDGES) return;
    int i = g_ei[warp];
    int j = g_ei[E_EDGES + warp];
    uint4 a = ((const uint4*)(g_zb + i * F_DIM))[lane];
    uint4 b = ((const uint4*)(g_zb + j * F_DIM))[lane];
    float acc;
    {
        float2 a0 = __bfloat1622float2(*(__nv_bfloat162*)&a.x);
        float2 a1 = __bfloat1622float2(*(__nv_bfloat162*)&a.y);
        float2 a2 = __bfloat1622float2(*(__nv_bfloat162*)&a.z);
        float2 a3 = __bfloat1622float2(*(__nv_bfloat162*)&a.w);
        float2 b0 = __bfloat1622float2(*(__nv_bfloat162*)&b.x);
        float2 b1 = __bfloat1622float2(*(__nv_bfloat162*)&b.y);
        float2 b2 = __bfloat1622float2(*(__nv_bfloat162*)&b.z);
        float2 b3 = __bfloat1622float2(*(__nv_bfloat162*)&b.w);
        acc = a0.x * b0.x + a0.y * b0.y + a1.x * b1.x + a1.y * b1.y
            + a2.x * b2.x + a2.y * b2.y + a3.x * b3.x + a3.y * b3.y;
    }
#pragma unroll
    for (int o = 16; o; o >>= 1) acc += __shfl_down_sync(0xffffffffu, acc, o);
    if (lane == 0) {
        float sim = acc / (g_nrm[i] * g_nrm[j]);
        atomicAdd(&g_scores[i], sim);
        atomicAdd(&g_deg[i], 1.0f);
    }
}

// ---------------- penalty GEMM (proven HMMA path) ---------------------------
__global__ void __launch_bounds__(256) penalty_mma_kernel() {
    extern __shared__ char smem[];
    uint32_t sb = smem_u32(smem);
    int t = threadIdx.x, wid = t >> 5, lane = t & 31;

    int rb = 0, cb;
    {
        int rem = blockIdx.x;
        int width = NTILES;
        while (rem >= width) { rem -= width; width--; rb++; }
        cb = rb + rem;
    }
    int r0 = rb * 128, c0 = cb * 128;
    int wm = (wid >> 2) * 64, wn = (wid & 3) * 32;
    float acc[4][4][4] = {};

    for (int ph = 0; ph < 2; ph++) {
        if (ph) __syncthreads();
        for (int q = t; q < 2048; q += 256) {
            int row = q >> 4, unit = q & 15;
            uint32_t off = (uint32_t)(row * 256 + ((unit ^ (row & 7)) << 4));
            *(uint4*)(smem + off) =
                *(const uint4*)(g_zb + (r0 + row) * F_DIM + ph * 128 + unit * 8);
            *(uint4*)(smem + PB_B_OFF + off) =
                *(const uint4*)(g_zb + (c0 + row) * F_DIM + ph * 128 + unit * 8);
        }
        __syncthreads();
        mma_tile_128(sb, wm, wn, lane, acc);
    }

    float psum = 0.f;
    int qr = lane >> 2, qc = (lane & 3) * 2;
    int wword = cb * 4 + (wid & 3);
#pragma unroll
    for (int mt = 0; mt < 4; mt++) {
        int lr0 = wm + mt * 16 + qr;
        unsigned w0 = g_adj[(r0 + lr0) * ADJ_ROW_WORDS + wword];
        unsigned w1 = g_adj[(r0 + lr0 + 8) * ADJ_ROW_WORDS + wword];
#pragma unroll
        for (int nt = 0; nt < 4; nt++) {
            int cbit = nt * 8 + qc;
            float v0 = acc[mt][nt][0], v1 = acc[mt][nt][1];
            float v2 = acc[mt][nt][2], v3 = acc[mt][nt][3];
            if (!((w0 >> cbit) & 1u) && v0 > 0.8f) psum += v0;
            if (!((w0 >> (cbit + 1)) & 1u) && v1 > 0.8f) psum += v1;
            if (!((w1 >> cbit) & 1u) && v2 > 0.8f) psum += v2;
            if (!((w1 >> (cbit + 1)) & 1u) && v3 > 0.8f) psum += v3;
        }
    }
#pragma unroll
    for (int o = 16; o; o >>= 1) psum += __shfl_down_sync(0xffffffffu, psum, o);
    __shared__ float red[8];
    if (lane == 0) red[wid] = psum;
    __syncthreads();
    if (t == 0) {
        float s = 0.f;
#pragma unroll
        for (int q = 0; q < 8; q++) s += red[q];
        double wgt = (rb == cb) ? 1.0 : 2.0;
        atomicAdd(&g_penalty, (double)s * wgt);
    }
}

// ---------------- finalize --------------------------------------------------
__global__ void final_kernel(float* __restrict__ out) {
    int t = threadIdx.x;
    float acc = 0.f;
    for (int n = t; n < N_NODES; n += 256) {
        float d = g_deg[n];
        if (d == 0.f) d = 1.f;
        acc += g_scores[n] / d;
    }
#pragma unroll
    for (int o = 16; o; o >>= 1) acc += __shfl_down_sync(0xffffffffu, acc, o);
    __shared__ float red[8];
    if ((t & 31) == 0) red[t >> 5] = acc;
    __syncthreads();
    if (t == 0) {
        float tot = 0.f;
        for (int q = 0; q < 8; q++) tot += red[q];
        double hom = -(double)tot / (double)N_NODES;
        double pen = g_penalty / ((double)N_NODES * (double)N_NODES);
        out[0] = (float)(hom + pen);
    }
}

// ---------------- launch ----------------------------------------------------
extern "C" void kernel_launch(void* const* d_in, const int* in_sizes, int n_in,
                              void* d_out, int out_size) {
    const float* z       = (const float*)d_in[0];
    const void*  ei_raw  = d_in[2];
    const void*  k2u_raw = d_in[3];
    const void*  u2k_raw = d_in[4];
    float* out = (float*)d_out;

    static int smem_set = 0;
    if (!smem_set) {
        cudaFuncSetAttribute(penalty_mma_kernel,
            cudaFuncAttributeMaxDynamicSharedMemorySize, PB_TOTAL);
        cudaFuncSetAttribute(cov_mma_kernel,
            cudaFuncAttributeMaxDynamicSharedMemorySize, PB_TOTAL);
        cudaFuncSetAttribute(z2_mma_kernel,
            cudaFuncAttributeMaxDynamicSharedMemorySize, PB_TOTAL);
        smem_set = 1;
    }

    detect_kernel<<<1, 128>>>(ei_raw);
    convert_kernel<<<(2 * E_EDGES + 255) / 256, 256>>>(ei_raw);
    zero_kernel<<<4096, 256>>>();
    mean_kernel<<<256, 256>>>(z);
    prep_kernel<<<32, 256>>>(k2u_raw, u2k_raw);
    prep2_kernel<<<128, 256>>>(z);
    cov_mma_kernel<<<dim3(3, 16), 256, PB_TOTAL>>>();
    cor_kernel<<<256, 256>>>();
    z2_mma_kernel<<<dim3(64, 2), 256, PB_TOTAL>>>(z);
    norm_kernel<<<N_NODES, 64>>>();
    adj_kernel<<<E_EDGES / 256, 256>>>();
    edge_kernel<<<E_EDGES * 32 / 256, 256>>>();
    penalty_mma_kernel<<<NPAIRS, 256, PB_TOTAL>>>();
    final_kernel<<<1, 256>>>(out);
}

// round 9
// speedup vs baseline: 3.9203x; 1.1881x over previous
#include <cuda_runtime.h>
#include <cuda_bf16.h>
#include <cstdint>

#define N_NODES 8192
#define F_DIM   256
#define E_EDGES 262144
#define ADJ_ROW_WORDS (N_NODES / 32)              // 256
#define ADJ_WORDS     (N_NODES * ADJ_ROW_WORDS)   // 8MB
#define PB_B_OFF 32768
#define PB_TOTAL 65536

// penalty: 256x128 tiles, upper-tri (cb >= 2*rb): 1056 tiles
#define PN_TILES 1056
#define PN_STAGE 98304                            // 64KB A + 32KB B
#define PN_B_OFF 65536
#define PN_TOTAL (2 * PN_STAGE)                   // 192KB

// ---------------- scratch ---------------------------------------------------
__device__ int           g_ei[2 * E_EDGES];
__device__ float         g_mean[F_DIM];
__device__ float         g_w[N_NODES];
__device__ float         g_cov[F_DIM * F_DIM];
__device__ __nv_bfloat16 g_corb[F_DIM * F_DIM];
__device__ __nv_bfloat16 g_zmt[F_DIM * N_NODES];       // zm^T bf16
__device__ __nv_bfloat16 g_wzmb[N_NODES * F_DIM];      // w*zm bf16
__device__ __nv_bfloat16 g_zb[N_NODES * F_DIM];        // z2 bf16
__device__ float         g_nrm[N_NODES];
__device__ unsigned      g_adj[ADJ_WORDS];
__device__ float         g_scores[N_NODES];
__device__ float         g_deg[N_NODES];
__device__ double        g_penalty;

__device__ __forceinline__ uint32_t smem_u32(const void* p) {
    uint32_t a;
    asm("{ .reg .u64 t; cvta.to.shared.u64 t, %1; cvt.u32.u64 %0, t; }"
        : "=r"(a) : "l"(p));
    return a;
}
__device__ __forceinline__ void cpa16(uint32_t saddr, const void* g) {
    asm volatile("cp.async.cg.shared.global [%0], [%1], 16;"
                 :: "r"(saddr), "l"(g));
}

// ---- HMMA inner loop for 128x128 tiles (cov / z2) ---------------------------
__device__ __forceinline__ void mma_tile_128(uint32_t sb, int wm, int wn,
                                             int lane, float acc[4][4][4]) {
#pragma unroll
    for (int ks = 0; ks < 128; ks += 16) {
        uint32_t a[4][4];
#pragma unroll
        for (int mt = 0; mt < 4; mt++) {
            int row = wm + mt * 16 + (lane & 15);
            int kc = ks + ((lane >> 4) << 3);
            uint32_t addr = sb + (uint32_t)(row * 256 +
                           ((((kc >> 3)) ^ (row & 7)) << 4));
            asm volatile(
                "ldmatrix.sync.aligned.m8n8.x4.shared.b16 {%0,%1,%2,%3}, [%4];"
                : "=r"(a[mt][0]), "=r"(a[mt][1]), "=r"(a[mt][2]), "=r"(a[mt][3])
                : "r"(addr));
        }
        uint32_t b[4][2];
#pragma unroll
        for (int pr = 0; pr < 2; pr++) {
            int row = wn + pr * 16 + ((lane >> 4) << 3) + (lane & 7);
            int kc = ks + (((lane >> 3) & 1) << 3);
            uint32_t addr = sb + PB_B_OFF + (uint32_t)(row * 256 +
                           ((((kc >> 3)) ^ (row & 7)) << 4));
            asm volatile(
                "ldmatrix.sync.aligned.m8n8.x4.shared.b16 {%0,%1,%2,%3}, [%4];"
                : "=r"(b[pr * 2][0]), "=r"(b[pr * 2][1]),
                  "=r"(b[pr * 2 + 1][0]), "=r"(b[pr * 2 + 1][1])
                : "r"(addr));
        }
#pragma unroll
        for (int mt = 0; mt < 4; mt++)
#pragma unroll
            for (int nt = 0; nt < 4; nt++)
                asm volatile(
                    "mma.sync.aligned.m16n8k16.row.col.f32.bf16.bf16.f32 "
                    "{%0,%1,%2,%3}, {%4,%5,%6,%7}, {%8,%9}, {%0,%1,%2,%3};"
                    : "+f"(acc[mt][nt][0]), "+f"(acc[mt][nt][1]),
                      "+f"(acc[mt][nt][2]), "+f"(acc[mt][nt][3])
                    : "r"(a[mt][0]), "r"(a[mt][1]), "r"(a[mt][2]), "r"(a[mt][3]),
                      "r"(b[nt][0]), "r"(b[nt][1]));
    }
}

// ---- HMMA inner loop for 256x128 tiles (penalty): warps 4(m) x 2(n) --------
__device__ __forceinline__ void mma_tile_256(uint32_t sbA, uint32_t sbB,
                                             int wm, int wn, int lane,
                                             float acc[4][8][4]) {
#pragma unroll
    for (int ks = 0; ks < 128; ks += 16) {
        uint32_t a[4][4];
#pragma unroll
        for (int mt = 0; mt < 4; mt++) {
            int row = wm + mt * 16 + (lane & 15);
            int kc = ks + ((lane >> 4) << 3);
            uint32_t addr = sbA + (uint32_t)(row * 256 +
                           ((((kc >> 3)) ^ (row & 7)) << 4));
            asm volatile(
                "ldmatrix.sync.aligned.m8n8.x4.shared.b16 {%0,%1,%2,%3}, [%4];"
                : "=r"(a[mt][0]), "=r"(a[mt][1]), "=r"(a[mt][2]), "=r"(a[mt][3])
                : "r"(addr));
        }
        uint32_t b[8][2];
#pragma unroll
        for (int pr = 0; pr < 4; pr++) {
            int row = wn + pr * 16 + ((lane >> 4) << 3) + (lane & 7);
            int kc = ks + (((lane >> 3) & 1) << 3);
            uint32_t addr = sbB + (uint32_t)(row * 256 +
                           ((((kc >> 3)) ^ (row & 7)) << 4));
            asm volatile(
                "ldmatrix.sync.aligned.m8n8.x4.shared.b16 {%0,%1,%2,%3}, [%4];"
                : "=r"(b[pr * 2][0]), "=r"(b[pr * 2][1]),
                  "=r"(b[pr * 2 + 1][0]), "=r"(b[pr * 2 + 1][1])
                : "r"(addr));
        }
#pragma unroll
        for (int mt = 0; mt < 4; mt++)
#pragma unroll
            for (int nt = 0; nt < 8; nt++)
                asm volatile(
                    "mma.sync.aligned.m16n8k16.row.col.f32.bf16.bf16.f32 "
                    "{%0,%1,%2,%3}, {%4,%5,%6,%7}, {%8,%9}, {%0,%1,%2,%3};"
                    : "+f"(acc[mt][nt][0]), "+f"(acc[mt][nt][1]),
                      "+f"(acc[mt][nt][2]), "+f"(acc[mt][nt][3])
                    : "r"(a[mt][0]), "r"(a[mt][1]), "r"(a[mt][2]), "r"(a[mt][3]),
                      "r"(b[nt][0]), "r"(b[nt][1]));
    }
}

// ---------------- zero scratch ----------------------------------------------
__global__ void zero_kernel() {
    int i = blockIdx.x * blockDim.x + threadIdx.x;
    int stride = gridDim.x * blockDim.x;
    for (int idx = i; idx < ADJ_WORDS; idx += stride) g_adj[idx] = 0u;
    for (int idx = i; idx < F_DIM * F_DIM; idx += stride) g_cov[idx] = 0.f;
    if (i < F_DIM) g_mean[i] = 0.f;
    if (i < N_NODES) { g_scores[i] = 0.f; g_deg[i] = 0.f; }
    if (i == 0) g_penalty = 0.0;
}

// ---------------- column sums -----------------------------------------------
__global__ void mean_kernel(const float* __restrict__ z) {
    int f = threadIdx.x;
    int r0 = blockIdx.x * 32;
    float acc = 0.f;
    for (int r = 0; r < 32; r++) acc += z[(r0 + r) * F_DIM + f];
    atomicAdd(&g_mean[f], acc);
}

// ---------------- convert edges + build adjacency (fused, self-detecting) ---
__global__ void convert_adj_kernel(const void* __restrict__ ei_raw) {
    const long long* p = (const long long*)ei_raw;
    int bad = 0;
    if (threadIdx.x < 128) {
        long long v = p[threadIdx.x];
        bad = (v < 0 || v >= N_NODES) ? 1 : 0;
    }
    bad = __syncthreads_or(bad);               // 1 => data is int32
    int e = blockIdx.x * blockDim.x + threadIdx.x;
    if (e >= E_EDGES) return;
    int i, j;
    if (bad) {
        i = ((const int*)ei_raw)[e];
        j = ((const int*)ei_raw)[E_EDGES + e];
    } else {
        i = (int)p[e];
        j = (int)p[E_EDGES + e];
    }
    i = min(max(i, 0), N_NODES - 1);
    j = min(max(j, 0), N_NODES - 1);
    g_ei[e] = i;
    g_ei[E_EDGES + e] = j;
    atomicOr(&g_adj[i * ADJ_ROW_WORDS + (j >> 5)], 1u << (j & 31));
    atomicOr(&g_adj[j * ADJ_ROW_WORDS + (i >> 5)], 1u << (i & 31));
}

// ---------------- scale mean + per-node weight (self-detecting dtype) -------
__global__ void prep_kernel(const void* __restrict__ ei_raw,
                            const void* __restrict__ k2u_raw,
                            const void* __restrict__ u2k_raw) {
    const long long* p = (const long long*)ei_raw;
    int bad = 0;
    if (threadIdx.x < 128) {
        long long v = p[threadIdx.x];
        bad = (v < 0 || v >= N_NODES) ? 1 : 0;
    }
    bad = __syncthreads_or(bad);
    int i = blockIdx.x * blockDim.x + threadIdx.x;
    if (i < F_DIM) g_mean[i] *= (1.f / (float)N_NODES);
    if (i < N_NODES) {
        float fa, fb;
        if (bad) {
            fa = (float)((const int*)k2u_raw)[i];
            fb = (float)((const int*)u2k_raw)[i];
        } else {
            fa = (float)((const long long*)k2u_raw)[i];
            fb = (float)((const long long*)u2k_raw)[i];
        }
        g_w[i] = powf(0.9f, fa) + 1.f - powf(0.9f, fb);
    }
}

// ---- build zm^T bf16 and w*zm bf16 -----------------------------------------
__global__ void prep2_kernel(const float* __restrict__ z) {
    __shared__ __nv_bfloat16 S[64][258];
    int n0 = blockIdx.x * 64;
    int t = threadIdx.x;
    for (int idx = t; idx < 64 * 256; idx += 256) {
        int nl = idx >> 8, f = idx & 255;
        float zm = z[(n0 + nl) * F_DIM + f] - g_mean[f];
        S[nl][f] = __float2bfloat16(zm);
        g_wzmb[(n0 + nl) * F_DIM + f] = __float2bfloat16(g_w[n0 + nl] * zm);
    }
    __syncthreads();
    for (int idx = t; idx < 256 * 64; idx += 256) {
        int f = idx >> 6, nl = idx & 63;
        g_zmt[f * N_NODES + n0 + nl] = S[nl][f];
    }
}

// ---- cov via HMMA: 3 symmetric tiles x 64 K-splits -------------------------
__global__ void __launch_bounds__(256) cov_mma_kernel() {
    extern __shared__ char smem[];
    uint32_t sb = smem_u32(smem);
    int t = threadIdx.x, wid = t >> 5, lane = t & 31;
    int tid = blockIdx.x;                    // 0:(0,0) 1:(0,1) 2:(1,1)
    int fb1 = (tid == 2) ? 1 : 0;
    int fb2 = (tid == 0) ? 0 : 1;
    int r0 = fb1 * 128, c0 = fb2 * 128;
    int k0 = blockIdx.y * 128;

    int wm = (wid >> 2) * 64, wn = (wid & 3) * 32;
    float acc[4][4][4] = {};

    for (int q = t; q < 2048; q += 256) {
        int row = q >> 4, unit = q & 15;
        uint32_t off = (uint32_t)(row * 256 + ((unit ^ (row & 7)) << 4));
        *(uint4*)(smem + off) =
            *(const uint4*)(g_zmt + (r0 + row) * N_NODES + k0 + unit * 8);
        *(uint4*)(smem + PB_B_OFF + off) =
            *(const uint4*)(g_zmt + (c0 + row) * N_NODES + k0 + unit * 8);
    }
    __syncthreads();
    mma_tile_128(sb, wm, wn, lane, acc);

    int qr = lane >> 2, qc = (lane & 3) * 2;
#pragma unroll
    for (int mt = 0; mt < 4; mt++) {
#pragma unroll
        for (int nt = 0; nt < 4; nt++) {
            int r = r0 + wm + mt * 16 + qr;
            int c = c0 + wn + nt * 8 + qc;
            float v0 = acc[mt][nt][0], v1 = acc[mt][nt][1];
            float v2 = acc[mt][nt][2], v3 = acc[mt][nt][3];
            atomicAdd(&g_cov[r * F_DIM + c], v0);
            atomicAdd(&g_cov[r * F_DIM + c + 1], v1);
            atomicAdd(&g_cov[(r + 8) * F_DIM + c], v2);
            atomicAdd(&g_cov[(r + 8) * F_DIM + c + 1], v3);
            if (tid == 1) {
                atomicAdd(&g_cov[c * F_DIM + r], v0);
                atomicAdd(&g_cov[(c + 1) * F_DIM + r], v1);
                atomicAdd(&g_cov[c * F_DIM + r + 8], v2);
                atomicAdd(&g_cov[(c + 1) * F_DIM + r + 8], v3);
            }
        }
    }
}

__global__ void cor_kernel() {
    int a = blockIdx.x, b = threadIdx.x;
    float denom = sqrtf(g_cov[a * F_DIM + a]) * sqrtf(g_cov[b * F_DIM + b]);
    float v = g_cov[a * F_DIM + b] / denom;
    if (isnan(v)) v = 0.f;
    v = fminf(1.f, fmaxf(-1.f, v));
    if (a == b) v = 0.f;
    g_corb[a * F_DIM + b] = __float2bfloat16(v);
}

// ---- z2 = z + EPS * (w*zm) @ cor via HMMA ----------------------------------
__global__ void __launch_bounds__(256) z2_mma_kernel(const float* __restrict__ z) {
    extern __shared__ char smem[];
    uint32_t sb = smem_u32(smem);
    int t = threadIdx.x, wid = t >> 5, lane = t & 31;
    int r0 = blockIdx.x * 128, c0 = blockIdx.y * 128;
    int wm = (wid >> 2) * 64, wn = (wid & 3) * 32;
    float acc[4][4][4] = {};

    for (int ph = 0; ph < 2; ph++) {
        if (ph) __syncthreads();
        for (int q = t; q < 2048; q += 256) {
            int row = q >> 4, unit = q & 15;
            uint32_t off = (uint32_t)(row * 256 + ((unit ^ (row & 7)) << 4));
            *(uint4*)(smem + off) =
                *(const uint4*)(g_wzmb + (r0 + row) * F_DIM + ph * 128 + unit * 8);
            *(uint4*)(smem + PB_B_OFF + off) =
                *(const uint4*)(g_corb + (c0 + row) * F_DIM + ph * 128 + unit * 8);
        }
        __syncthreads();
        mma_tile_128(sb, wm, wn, lane, acc);
    }

    int qr = lane >> 2, qc = (lane & 3) * 2;
#pragma unroll
    for (int mt = 0; mt < 4; mt++) {
#pragma unroll
        for (int nt = 0; nt < 4; nt++) {
            int r = r0 + wm + mt * 16 + qr;
            int c = c0 + wn + nt * 8 + qc;
            float v0 = z[r * F_DIM + c] + 0.01f * acc[mt][nt][0];
            float v1 = z[r * F_DIM + c + 1] + 0.01f * acc[mt][nt][1];
            float v2 = z[(r + 8) * F_DIM + c] + 0.01f * acc[mt][nt][2];
            float v3 = z[(r + 8) * F_DIM + c + 1] + 0.01f * acc[mt][nt][3];
            *(__nv_bfloat162*)(g_zb + r * F_DIM + c) = __floats2bfloat162_rn(v0, v1);
            *(__nv_bfloat162*)(g_zb + (r + 8) * F_DIM + c) = __floats2bfloat162_rn(v2, v3);
        }
    }
}

// ---------------- per-node L2 norm ------------------------------------------
__global__ void norm_kernel() {
    int n = blockIdx.x;
    int t = threadIdx.x;                       // 64 threads
    uint4 v = ((const uint4*)(g_zb + n * F_DIM))[t];
    float s;
    {
        float2 f0 = __bfloat1622float2(*(__nv_bfloat162*)&v.x);
        float2 f1 = __bfloat1622float2(*(__nv_bfloat162*)&v.y);
        float2 f2 = __bfloat1622float2(*(__nv_bfloat162*)&v.z);
        float2 f3 = __bfloat1622float2(*(__nv_bfloat162*)&v.w);
        s = f0.x * f0.x + f0.y * f0.y + f1.x * f1.x + f1.y * f1.y
          + f2.x * f2.x + f2.y * f2.y + f3.x * f3.x + f3.y * f3.y;
    }
#pragma unroll
    for (int o = 16; o; o >>= 1) s += __shfl_down_sync(0xffffffffu, s, o);
    __shared__ float sw[2];
    if ((t & 31) == 0) sw[t >> 5] = s;
    __syncthreads();
    if (t == 0) g_nrm[n] = fmaxf(sqrtf(sw[0] + sw[1]), 1e-8f);
}

// ---------------- per-edge cosine -------------------------------------------
__global__ void edge_kernel() {
    int warp = (blockIdx.x * blockDim.x + threadIdx.x) >> 5;
    int lane = threadIdx.x & 31;
    if (warp >= E_EDGES) return;
    int i = g_ei[warp];
    int j = g_ei[E_EDGES + warp];
    uint4 a = ((const uint4*)(g_zb + i * F_DIM))[lane];
    uint4 b = ((const uint4*)(g_zb + j * F_DIM))[lane];
    float acc;
    {
        float2 a0 = __bfloat1622float2(*(__nv_bfloat162*)&a.x);
        float2 a1 = __bfloat1622float2(*(__nv_bfloat162*)&a.y);
        float2 a2 = __bfloat1622float2(*(__nv_bfloat162*)&a.z);
        float2 a3 = __bfloat1622float2(*(__nv_bfloat162*)&a.w);
        float2 b0 = __bfloat1622float2(*(__nv_bfloat162*)&b.x);
        float2 b1 = __bfloat1622float2(*(__nv_bfloat162*)&b.y);
        float2 b2 = __bfloat1622float2(*(__nv_bfloat162*)&b.z);
        float2 b3 = __bfloat1622float2(*(__nv_bfloat162*)&b.w);
        acc = a0.x * b0.x + a0.y * b0.y + a1.x * b1.x + a1.y * b1.y
            + a2.x * b2.x + a2.y * b2.y + a3.x * b3.x + a3.y * b3.y;
    }
#pragma unroll
    for (int o = 16; o; o >>= 1) acc += __shfl_down_sync(0xffffffffu, acc, o);
    if (lane == 0) {
        float sim = acc / (g_nrm[i] * g_nrm[j]);
        atomicAdd(&g_scores[i], sim);
        atomicAdd(&g_deg[i], 1.0f);
    }
}

// ---------------- penalty: 256x128 tiles, cp.async pipelined ----------------
__global__ void __launch_bounds__(256) penalty_mma_kernel() {
    extern __shared__ char smem[];
    uint32_t sb = smem_u32(smem);
    int t = threadIdx.x, wid = t >> 5, lane = t & 31;

    // decode linear index -> (rb, cb) with cb >= 2*rb; widths 64-2rb
    int rb = 0, cb;
    {
        int rem = blockIdx.x;
        int width = 64;
        while (rem >= width) { rem -= width; width -= 2; rb++; }
        cb = 2 * rb + rem;
    }
    int r0 = rb * 256, c0 = cb * 128;
    int wm = (wid >> 1) * 64, wn = (wid & 1) * 64;

    float acc[4][8][4] = {};

    // issue both stages' loads via cp.async
#pragma unroll
    for (int ph = 0; ph < 2; ph++) {
        uint32_t stage = ph * PN_STAGE;
        for (int q = t; q < 4096; q += 256) {           // A: 256 rows
            int row = q >> 4, unit = q & 15;
            uint32_t off = stage + (uint32_t)(row * 256 + ((unit ^ (row & 7)) << 4));
            cpa16(sb + off, g_zb + (r0 + row) * F_DIM + ph * 128 + unit * 8);
        }
        for (int q = t; q < 2048; q += 256) {           // B: 128 rows
            int row = q >> 4, unit = q & 15;
            uint32_t off = stage + PN_B_OFF +
                           (uint32_t)(row * 256 + ((unit ^ (row & 7)) << 4));
            cpa16(sb + off, g_zb + (c0 + row) * F_DIM + ph * 128 + unit * 8);
        }
        asm volatile("cp.async.commit_group;" ::: "memory");
    }

    asm volatile("cp.async.wait_group 1;" ::: "memory");
    __syncthreads();
    mma_tile_256(sb, sb + PN_B_OFF, wm, wn, lane, acc);
    asm volatile("cp.async.wait_group 0;" ::: "memory");
    __syncthreads();
    mma_tile_256(sb + PN_STAGE, sb + PN_STAGE + PN_B_OFF, wm, wn, lane, acc);

    // epilogue: per-element symmetric weight + adjacency + threshold
    float psum = 0.f;
    int qr = lane >> 2, qc = (lane & 3) * 2;
    int wbase = cb * 4 + (wn >> 5);
#pragma unroll
    for (int mt = 0; mt < 4; mt++) {
        int lr = wm + mt * 16 + qr;
        int gi0 = r0 + lr, gi1 = gi0 + 8;
        unsigned a00 = g_adj[gi0 * ADJ_ROW_WORDS + wbase];
        unsigned a01 = g_adj[gi0 * ADJ_ROW_WORDS + wbase + 1];
        unsigned a10 = g_adj[gi1 * ADJ_ROW_WORDS + wbase];
        unsigned a11 = g_adj[gi1 * ADJ_ROW_WORDS + wbase + 1];
#pragma unroll
        for (int nt = 0; nt < 8; nt++) {
            int bit = (nt & 3) * 8 + qc;
            unsigned w0 = (nt < 4) ? a00 : a01;
            unsigned w1 = (nt < 4) ? a10 : a11;
            int gj = c0 + wn + nt * 8 + qc;
            float v0 = acc[mt][nt][0], v1 = acc[mt][nt][1];
            float v2 = acc[mt][nt][2], v3 = acc[mt][nt][3];
            float wf00 = (gj > gi0) ? 2.f : ((gj == gi0) ? 1.f : 0.f);
            float wf01 = (gj + 1 > gi0) ? 2.f : ((gj + 1 == gi0) ? 1.f : 0.f);
            float wf10 = (gj > gi1) ? 2.f : ((gj == gi1) ? 1.f : 0.f);
            float wf11 = (gj + 1 > gi1) ? 2.f : ((gj + 1 == gi1) ? 1.f : 0.f);
            if (!((w0 >> bit) & 1u) && v0 > 0.8f) psum += v0 * wf00;
            if (!((w0 >> (bit + 1)) & 1u) && v1 > 0.8f) psum += v1 * wf01;
            if (!((w1 >> bit) & 1u) && v2 > 0.8f) psum += v2 * wf10;
            if (!((w1 >> (bit + 1)) & 1u) && v3 > 0.8f) psum += v3 * wf11;
        }
    }
#pragma unroll
    for (int o = 16; o; o >>= 1) psum += __shfl_down_sync(0xffffffffu, psum, o);
    __shared__ float red[8];
    if (lane == 0) red[wid] = psum;
    __syncthreads();
    if (t == 0) {
        float s = 0.f;
#pragma unroll
        for (int q = 0; q < 8; q++) s += red[q];
        atomicAdd(&g_penalty, (double)s);
    }
}

// ---------------- finalize --------------------------------------------------
__global__ void final_kernel(float* __restrict__ out) {
    int t = threadIdx.x;
    float acc = 0.f;
    for (int n = t; n < N_NODES; n += 256) {
        float d = g_deg[n];
        if (d == 0.f) d = 1.f;
        acc += g_scores[n] / d;
    }
#pragma unroll
    for (int o = 16; o; o >>= 1) acc += __shfl_down_sync(0xffffffffu, acc, o);
    __shared__ float red[8];
    if ((t & 31) == 0) red[t >> 5] = acc;
    __syncthreads();
    if (t == 0) {
        float tot = 0.f;
        for (int q = 0; q < 8; q++) tot += red[q];
        double hom = -(double)tot / (double)N_NODES;
        double pen = g_penalty / ((double)N_NODES * (double)N_NODES);
        out[0] = (float)(hom + pen);
    }
}

// ---------------- launch ----------------------------------------------------
extern "C" void kernel_launch(void* const* d_in, const int* in_sizes, int n_in,
                              void* d_out, int out_size) {
    const float* z       = (const float*)d_in[0];
    const void*  ei_raw  = d_in[2];
    const void*  k2u_raw = d_in[3];
    const void*  u2k_raw = d_in[4];
    float* out = (float*)d_out;

    static int smem_set = 0;
    if (!smem_set) {
        cudaFuncSetAttribute(penalty_mma_kernel,
            cudaFuncAttributeMaxDynamicSharedMemorySize, PN_TOTAL);
        cudaFuncSetAttribute(cov_mma_kernel,
            cudaFuncAttributeMaxDynamicSharedMemorySize, PB_TOTAL);
        cudaFuncSetAttribute(z2_mma_kernel,
            cudaFuncAttributeMaxDynamicSharedMemorySize, PB_TOTAL);
        smem_set = 1;
    }

    zero_kernel<<<4096, 256>>>();
    mean_kernel<<<256, 256>>>(z);
    convert_adj_kernel<<<(E_EDGES + 255) / 256, 256>>>(ei_raw);
    prep_kernel<<<32, 256>>>(ei_raw, k2u_raw, u2k_raw);
    prep2_kernel<<<128, 256>>>(z);
    cov_mma_kernel<<<dim3(3, 64), 256, PB_TOTAL>>>();
    cor_kernel<<<256, 256>>>();
    z2_mma_kernel<<<dim3(64, 2), 256, PB_TOTAL>>>(z);
    norm_kernel<<<N_NODES, 64>>>();
    edge_kernel<<<E_EDGES * 32 / 256, 256>>>();
    penalty_mma_kernel<<<PN_TILES, 256, PN_TOTAL>>>();
    final_kernel<<<1, 256>>>(out);
}